// round 7
// baseline (speedup 1.0000x reference)
#include <cuda_runtime.h>
#include <cuda_fp16.h>
#include <math.h>
#include <stdint.h>

// ---------------- problem constants -----------------------------------------
#define TOKENS 4096
#define DDIM   1024
#define FDIM   4096
#define NEXP   8
#define PAIRS  (TOKENS * 2)
#define CAP    TOKENS

// ---------------- GEMM tiling ------------------------------------------------
#define BM 128
#define BN 128
#define BK 32
#define NTH 128                        // 4 warps, 2x2, warp tile 64x64
#define LDT 40                         // padded smem stride (halves) = 80 B
#define A_BYTES  (BM * LDT * 2)        // 10240
#define STAGE_BYTES (2 * BM * LDT * 2) // A + B = 20480
#define SOFF_STAGE 1024
#define SMEM_BYTES (SOFF_STAGE + 2 * STAGE_BYTES)  // 41984

// ---------------- scratch (72 MB — proven budget) -------------------------------
__device__ int    g_counts[NEXP];
__device__ int    g_list[NEXP * CAP];
__device__ float  g_prob[PAIRS];
__device__ __half g_xf[(size_t)TOKENS * DDIM];   // fp16 x  (8 MB)
__device__ __half g_hf[(size_t)PAIRS * FDIM];    // fp16 h  (64 MB)

// ---------------- ptx helpers --------------------------------------------------
__device__ __forceinline__ uint32_t smem_u32(const void* p) {
    uint32_t a;
    asm("{ .reg .u64 t; cvta.to.shared.u64 t, %1; cvt.u32.u64 %0, t; }"
        : "=r"(a) : "l"(p));
    return a;
}
__device__ __forceinline__ void cp16(uint32_t dst, const void* src) {
    asm volatile("cp.async.cg.shared.global [%0], [%1], 16;" :: "r"(dst), "l"(src));
}
__device__ __forceinline__ void cp_commit() {
    asm volatile("cp.async.commit_group;" ::: "memory");
}
template <int N>
__device__ __forceinline__ void cp_wait() {
    asm volatile("cp.async.wait_group %0;" :: "n"(N) : "memory");
}
__device__ __forceinline__ void ldm4(uint32_t* r, uint32_t a) {
    asm volatile("ldmatrix.sync.aligned.m8n8.x4.shared.b16 {%0,%1,%2,%3}, [%4];"
                 : "=r"(r[0]), "=r"(r[1]), "=r"(r[2]), "=r"(r[3]) : "r"(a));
}
__device__ __forceinline__ void mma_f16(float* c, const uint32_t* a, const uint32_t* b) {
    asm volatile(
        "mma.sync.aligned.m16n8k16.row.col.f32.f16.f16.f32 "
        "{%0,%1,%2,%3}, {%4,%5,%6,%7}, {%8,%9}, {%0,%1,%2,%3};"
        : "+f"(c[0]), "+f"(c[1]), "+f"(c[2]), "+f"(c[3])
        : "r"(a[0]), "r"(a[1]), "r"(a[2]), "r"(a[3]), "r"(b[0]), "r"(b[1]));
}

// ---------------- math helpers --------------------------------------------------
__device__ __forceinline__ float gelu_tanh(float v) {
    const float c = 0.7978845608028654f;
    float u = c * (v + 0.044715f * v * v * v);
    return 0.5f * v * (1.0f + tanhf(u));
}
__device__ __forceinline__ void conv_sts(char* smem, uint32_t off, float4 v) {
    __half2 h0 = __halves2half2(__float2half_rn(v.x), __float2half_rn(v.y));
    __half2 h1 = __halves2half2(__float2half_rn(v.z), __float2half_rn(v.w));
    *reinterpret_cast<uint2*>(smem + off) =
        make_uint2(*(uint32_t*)&h0, *(uint32_t*)&h1);
}

// ---------------- kernel 0: zero output + counts --------------------------------
__global__ void zero_kernel(float* __restrict__ out, int n) {
    int i = blockIdx.x * blockDim.x + threadIdx.x;
    if (i < n) out[i] = 0.0f;
    if (blockIdx.x == 0 && threadIdx.x < NEXP) g_counts[threadIdx.x] = 0;
}

// ---------------- kernel: gate + x->fp16 convert (fused) -------------------------
__global__ __launch_bounds__(256) void gate_kernel(
    const float* __restrict__ x, const float* __restrict__ gw)
{
    int t = blockIdx.x;
    const float* xr = x + (size_t)t * DDIM;

    float acc[NEXP];
#pragma unroll
    for (int e = 0; e < NEXP; e++) acc[e] = 0.0f;
    for (int d = threadIdx.x; d < DDIM; d += 256) {
        float xv = xr[d];
        g_xf[(size_t)t * DDIM + d] = __float2half_rn(xv);
#pragma unroll
        for (int e = 0; e < NEXP; e++) acc[e] += xv * gw[e * DDIM + d];
    }
#pragma unroll
    for (int e = 0; e < NEXP; e++) {
#pragma unroll
        for (int o = 16; o > 0; o >>= 1)
            acc[e] += __shfl_xor_sync(0xffffffff, acc[e], o);
    }
    __shared__ float red[NEXP][8];
    int warp = threadIdx.x >> 5, lane = threadIdx.x & 31;
    if (lane == 0) {
#pragma unroll
        for (int e = 0; e < NEXP; e++) red[e][warp] = acc[e];
    }
    __syncthreads();
    if (threadIdx.x == 0) {
        float lg[NEXP];
#pragma unroll
        for (int e = 0; e < NEXP; e++) {
            float s = 0.0f;
#pragma unroll
            for (int w = 0; w < 8; w++) s += red[e][w];
            lg[e] = s;
        }
        float mx = lg[0];
#pragma unroll
        for (int e = 1; e < NEXP; e++) mx = fmaxf(mx, lg[e]);
        float pe[NEXP], s = 0.0f;
#pragma unroll
        for (int e = 0; e < NEXP; e++) { pe[e] = expf(lg[e] - mx); s += pe[e]; }
        float inv = 1.0f / s;
        int i0 = 0;
#pragma unroll
        for (int e = 1; e < NEXP; e++) if (pe[e] > pe[i0]) i0 = e;
        int i1 = (i0 == 0) ? 1 : 0;
#pragma unroll
        for (int e = 0; e < NEXP; e++)
            if (e != i0 && pe[e] > pe[i1]) i1 = e;
        int p0 = t * 2, p1 = t * 2 + 1;
        g_prob[p0] = pe[i0] * inv;
        g_prob[p1] = pe[i1] * inv;
        int pos0 = atomicAdd(&g_counts[i0], 1);
        g_list[i0 * CAP + pos0] = p0;
        int pos1 = atomicAdd(&g_counts[i1], 1);
        g_list[i1 * CAP + pos1] = p1;
    }
}

// ---------------- grouped single-pass fp16 GEMM, 64x64 warp tiles ------------------
template <int KDIM, bool L2TAG>
__global__ __launch_bounds__(NTH, 2)
void moe_fp16(const float* __restrict__ W,
              const float* __restrict__ bias,
              float* __restrict__ dout)
{
    int e   = blockIdx.z;
    int cnt = g_counts[e];
    int m0  = blockIdx.y * BM;
    if (m0 >= cnt) return;
    int n0  = blockIdx.x * BN;

    extern __shared__ __align__(128) char smem[];
    uint32_t sb = smem_u32(smem);
    int* rows = (int*)smem;

    int tid = threadIdx.x, wid = tid >> 5, lane = tid & 31;

    {
        int m = m0 + tid;
        rows[tid] = g_list[e * CAP + (m < cnt ? m : m0)];
    }
    __syncthreads();

    // ---- A: cp.async mapping (1 row, 4 x 16B per thread) ----
    int pa = rows[tid];
    const __half* a_row = L2TAG ? (g_hf + (size_t)pa * KDIM)
                                : (g_xf + (size_t)(pa >> 1) * KDIM);
    const char* a_src = (const char*)a_row;
    uint32_t a_dst = sb + SOFF_STAGE + (uint32_t)tid * 80;

    // ---- W: LDG float4 mapping (8 per thread, 4 rows/warp coalesced) ----
    const float* wp[8];
    uint32_t woff[8];
#pragma unroll
    for (int j = 0; j < 8; j++) {
        int s = tid + j * 128;
        int r = s >> 3;
        int k4 = (s & 7) << 2;
        wp[j] = W + ((size_t)(n0 + r) * NEXP + e) * KDIM + k4;
        woff[j] = (uint32_t)r * 80 + (uint32_t)k4 * 2;
    }

    constexpr int NCH = KDIM / BK;

    // ---- fragment addressing: 2x2 warps, warp tile 64x64 ----
    int wm = wid & 1, wn = wid >> 1;
    int li = lane >> 3, lr = lane & 7;
    uint32_t aoff = (uint32_t)((wm * 64 + lr + (li & 1) * 8) * 80 + (li >> 1) * 16);
    uint32_t boff = (uint32_t)((wn * 64 + (li >> 1) * 8 + lr) * 80 + (li & 1) * 16);

    float acc[4][8][4];
#pragma unroll
    for (int im = 0; im < 4; im++)
#pragma unroll
        for (int in = 0; in < 8; in++)
#pragma unroll
            for (int q = 0; q < 4; q++) acc[im][in][q] = 0.0f;

    // ---- prologue ----
#pragma unroll
    for (int q = 0; q < 4; q++) cp16(a_dst + q * 16, a_src + q * 16);
    cp_commit();
    float4 wreg[8];
#pragma unroll
    for (int j = 0; j < 8; j++) wreg[j] = *(const float4*)(wp[j]);

    for (int i = 0; i < NCH; i++) {
        uint32_t st = sb + SOFF_STAGE + (uint32_t)(i & 1) * STAGE_BYTES;
        char* stc = smem + SOFF_STAGE + (size_t)(i & 1) * STAGE_BYTES;

        // stage W chunk i (fp32 -> fp16)
#pragma unroll
        for (int j = 0; j < 8; j++)
            conv_sts(stc, A_BYTES + woff[j], wreg[j]);

        cp_wait<0>();
        __syncthreads();

        // issue A chunk i+1 into the other buffer
        if (i + 1 < NCH) {
            uint32_t nst = sb + SOFF_STAGE + (uint32_t)((i + 1) & 1) * STAGE_BYTES
                         + (uint32_t)tid * 80;
            int kb = (i + 1) * BK * 2;
#pragma unroll
            for (int q = 0; q < 4; q++) cp16(nst + q * 16, a_src + kb + q * 16);
        }
        cp_commit();

        // prefetch W chunk i+1
        if (i + 1 < NCH) {
            int k0 = (i + 1) * BK;
#pragma unroll
            for (int j = 0; j < 8; j++) wreg[j] = *(const float4*)(wp[j] + k0);
        }

        // compute chunk i
        uint32_t As = st, Bs = st + A_BYTES;
#pragma unroll
        for (int kk = 0; kk < BK; kk += 16) {
            uint32_t bf[8][2];
#pragma unroll
            for (int h = 0; h < 4; h++) {
                uint32_t t4[4];
                ldm4(t4, Bs + boff + h * 1280 + kk * 2);
                bf[2 * h][0] = t4[0]; bf[2 * h][1] = t4[1];
                bf[2 * h + 1][0] = t4[2]; bf[2 * h + 1][1] = t4[3];
            }
#pragma unroll
            for (int im = 0; im < 4; im++) {
                uint32_t af[4];
                ldm4(af, As + aoff + im * 1280 + kk * 2);
#pragma unroll
                for (int in = 0; in < 8; in++)
                    mma_f16(acc[im][in], af, bf[in]);
            }
        }
    }

    // ---- epilogue ----
    int qr = lane >> 2, qc = (lane & 3) * 2;
#pragma unroll
    for (int im = 0; im < 4; im++) {
#pragma unroll
        for (int half = 0; half < 2; half++) {
            int m_loc = wm * 64 + im * 16 + qr + half * 8;
            if (m0 + m_loc >= cnt) continue;
            int p = rows[m_loc];
            if (!L2TAG) {
                __half* hp = g_hf + (size_t)p * FDIM;
                const float* bb = bias + (size_t)e * FDIM;
#pragma unroll
                for (int in = 0; in < 8; in++) {
                    int col = n0 + wn * 64 + in * 8 + qc;
                    float v0 = acc[im][in][half * 2 + 0] + bb[col];
                    float v1 = acc[im][in][half * 2 + 1] + bb[col + 1];
                    __half2 hv = __halves2half2(__float2half_rn(gelu_tanh(v0)),
                                                __float2half_rn(gelu_tanh(v1)));
                    *reinterpret_cast<uint32_t*>(hp + col) = *(uint32_t*)&hv;
                }
            } else {
                float pr = g_prob[p];
                float* op = dout + (size_t)(p >> 1) * DDIM;
                const float* bb = bias + (size_t)e * DDIM;
#pragma unroll
                for (int in = 0; in < 8; in++) {
                    int col = n0 + wn * 64 + in * 8 + qc;
                    atomicAdd(&op[col],
                              pr * (acc[im][in][half * 2 + 0] + bb[col]));
                    atomicAdd(&op[col + 1],
                              pr * (acc[im][in][half * 2 + 1] + bb[col + 1]));
                }
            }
        }
    }
}

// ---------------- launch --------------------------------------------------------------
extern "C" void kernel_launch(void* const* d_in, const int* in_sizes, int n_in,
                              void* d_out, int out_size)
{
    (void)in_sizes; (void)n_in; (void)out_size;
    const float* x  = (const float*)d_in[0];
    const float* gw = (const float*)d_in[1];
    const float* w1 = (const float*)d_in[2];
    const float* b1 = (const float*)d_in[3];
    const float* w2 = (const float*)d_in[4];
    const float* b2 = (const float*)d_in[5];
    float* out = (float*)d_out;

    cudaFuncSetAttribute(moe_fp16<DDIM, false>,
                         cudaFuncAttributeMaxDynamicSharedMemorySize, SMEM_BYTES);
    cudaFuncSetAttribute(moe_fp16<FDIM, true>,
                         cudaFuncAttributeMaxDynamicSharedMemorySize, SMEM_BYTES);

    zero_kernel<<<(TOKENS * DDIM + 255) / 256, 256>>>(out, TOKENS * DDIM);
    gate_kernel<<<TOKENS, 256>>>(x, gw);

    dim3 g1(FDIM / BN, TOKENS / BM, NEXP);   // 32 x 32 x 8
    moe_fp16<DDIM, false><<<g1, NTH, SMEM_BYTES>>>(w1, b1, nullptr);

    dim3 g2(DDIM / BN, TOKENS / BM, NEXP);   // 8 x 32 x 8
    moe_fp16<FDIM, true><<<g2, NTH, SMEM_BYTES>>>(w2, b2, out);
}

// round 8
// speedup vs baseline: 1.0987x; 1.0987x over previous
#include <cuda_runtime.h>
#include <cuda_fp16.h>
#include <math.h>
#include <stdint.h>

// ---------------- problem constants -----------------------------------------
#define TOKENS 4096
#define DDIM   1024
#define FDIM   4096
#define NEXP   8
#define PAIRS  (TOKENS * 2)
#define CAP    TOKENS

// ---------------- GEMM tiling ------------------------------------------------
#define BM 128
#define BN 128
#define BK 32
#define NTH 256                        // 8 warps, 2(m) x 4(n), warp tile 64x32
#define LDT 40                         // padded smem stride (halves) = 80 B
#define A_BYTES  (BM * LDT * 2)        // 10240
#define STAGE_BYTES (2 * BM * LDT * 2) // A + B = 20480
#define SOFF_STAGE 1024
#define SMEM_BYTES (SOFF_STAGE + 2 * STAGE_BYTES)  // 41984

// ---------------- scratch (72 MB — proven budget) -------------------------------
__device__ int    g_counts[NEXP];
__device__ int    g_list[NEXP * CAP];
__device__ float  g_prob[PAIRS];
__device__ __half g_xf[(size_t)TOKENS * DDIM];   // fp16 x  (8 MB)
__device__ __half g_hf[(size_t)PAIRS * FDIM];    // fp16 h  (64 MB)

// ---------------- ptx helpers --------------------------------------------------
__device__ __forceinline__ uint32_t smem_u32(const void* p) {
    uint32_t a;
    asm("{ .reg .u64 t; cvta.to.shared.u64 t, %1; cvt.u32.u64 %0, t; }"
        : "=r"(a) : "l"(p));
    return a;
}
__device__ __forceinline__ void cp16(uint32_t dst, const void* src) {
    asm volatile("cp.async.cg.shared.global [%0], [%1], 16;" :: "r"(dst), "l"(src));
}
__device__ __forceinline__ void cp_commit() {
    asm volatile("cp.async.commit_group;" ::: "memory");
}
template <int N>
__device__ __forceinline__ void cp_wait() {
    asm volatile("cp.async.wait_group %0;" :: "n"(N) : "memory");
}
__device__ __forceinline__ void ldm4(uint32_t* r, uint32_t a) {
    asm volatile("ldmatrix.sync.aligned.m8n8.x4.shared.b16 {%0,%1,%2,%3}, [%4];"
                 : "=r"(r[0]), "=r"(r[1]), "=r"(r[2]), "=r"(r[3]) : "r"(a));
}
__device__ __forceinline__ void mma_f16(float* c, const uint32_t* a, const uint32_t* b) {
    asm volatile(
        "mma.sync.aligned.m16n8k16.row.col.f32.f16.f16.f32 "
        "{%0,%1,%2,%3}, {%4,%5,%6,%7}, {%8,%9}, {%0,%1,%2,%3};"
        : "+f"(c[0]), "+f"(c[1]), "+f"(c[2]), "+f"(c[3])
        : "r"(a[0]), "r"(a[1]), "r"(a[2]), "r"(a[3]), "r"(b[0]), "r"(b[1]));
}

// ---------------- math helpers --------------------------------------------------
__device__ __forceinline__ float gelu_tanh(float v) {
    const float c = 0.7978845608028654f;
    float u = c * (v + 0.044715f * v * v * v);
    return 0.5f * v * (1.0f + tanhf(u));
}
__device__ __forceinline__ void conv_sts(char* smem, uint32_t off, float4 v) {
    __half2 h0 = __halves2half2(__float2half_rn(v.x), __float2half_rn(v.y));
    __half2 h1 = __halves2half2(__float2half_rn(v.z), __float2half_rn(v.w));
    *reinterpret_cast<uint2*>(smem + off) =
        make_uint2(*(uint32_t*)&h0, *(uint32_t*)&h1);
}

// ---------------- kernel 0: zero output + counts --------------------------------
__global__ void zero_kernel(float* __restrict__ out, int n) {
    int i = blockIdx.x * blockDim.x + threadIdx.x;
    if (i < n) out[i] = 0.0f;
    if (blockIdx.x == 0 && threadIdx.x < NEXP) g_counts[threadIdx.x] = 0;
}

// ---------------- kernel: gate + x->fp16 convert (fused) -------------------------
__global__ __launch_bounds__(256) void gate_kernel(
    const float* __restrict__ x, const float* __restrict__ gw)
{
    int t = blockIdx.x;
    const float* xr = x + (size_t)t * DDIM;

    float acc[NEXP];
#pragma unroll
    for (int e = 0; e < NEXP; e++) acc[e] = 0.0f;
    for (int d = threadIdx.x; d < DDIM; d += 256) {
        float xv = xr[d];
        g_xf[(size_t)t * DDIM + d] = __float2half_rn(xv);
#pragma unroll
        for (int e = 0; e < NEXP; e++) acc[e] += xv * gw[e * DDIM + d];
    }
#pragma unroll
    for (int e = 0; e < NEXP; e++) {
#pragma unroll
        for (int o = 16; o > 0; o >>= 1)
            acc[e] += __shfl_xor_sync(0xffffffff, acc[e], o);
    }
    __shared__ float red[NEXP][8];
    int warp = threadIdx.x >> 5, lane = threadIdx.x & 31;
    if (lane == 0) {
#pragma unroll
        for (int e = 0; e < NEXP; e++) red[e][warp] = acc[e];
    }
    __syncthreads();
    if (threadIdx.x == 0) {
        float lg[NEXP];
#pragma unroll
        for (int e = 0; e < NEXP; e++) {
            float s = 0.0f;
#pragma unroll
            for (int w = 0; w < 8; w++) s += red[e][w];
            lg[e] = s;
        }
        float mx = lg[0];
#pragma unroll
        for (int e = 1; e < NEXP; e++) mx = fmaxf(mx, lg[e]);
        float pe[NEXP], s = 0.0f;
#pragma unroll
        for (int e = 0; e < NEXP; e++) { pe[e] = expf(lg[e] - mx); s += pe[e]; }
        float inv = 1.0f / s;
        int i0 = 0;
#pragma unroll
        for (int e = 1; e < NEXP; e++) if (pe[e] > pe[i0]) i0 = e;
        int i1 = (i0 == 0) ? 1 : 0;
#pragma unroll
        for (int e = 0; e < NEXP; e++)
            if (e != i0 && pe[e] > pe[i1]) i1 = e;
        int p0 = t * 2, p1 = t * 2 + 1;
        g_prob[p0] = pe[i0] * inv;
        g_prob[p1] = pe[i1] * inv;
        int pos0 = atomicAdd(&g_counts[i0], 1);
        g_list[i0 * CAP + pos0] = p0;
        int pos1 = atomicAdd(&g_counts[i1], 1);
        g_list[i1 * CAP + pos1] = p1;
    }
}

// ---------------- grouped single-pass fp16 GEMM (R6 shape + k-split + bf prefetch)
// KSPLIT: L2 splits K across 2 blocks (atomicAdd partials; bias from ks==0 only).
template <int KDIM, bool L2TAG>
__global__ __launch_bounds__(NTH, 2)
void moe_fp16(const float* __restrict__ W,
              const float* __restrict__ bias,
              float* __restrict__ dout)
{
    constexpr int KSPLIT = L2TAG ? 2 : 1;
    constexpr int KLOC = KDIM / KSPLIT;

    int e   = blockIdx.z;
    int cnt = g_counts[e];
    int m0  = blockIdx.y * BM;
    if (m0 >= cnt) return;
    int ks    = blockIdx.x % KSPLIT;
    int n0    = (blockIdx.x / KSPLIT) * BN;
    int kbase = ks * KLOC;

    extern __shared__ __align__(128) char smem[];
    uint32_t sb = smem_u32(smem);
    int* rows = (int*)smem;

    int tid = threadIdx.x, wid = tid >> 5, lane = tid & 31;

    if (tid < BM) {
        int m = m0 + tid;
        rows[tid] = g_list[e * CAP + (m < cnt ? m : m0)];
    }
    __syncthreads();

    // ---- A: cp.async mapping (2 x 16B per thread) ----
    int arow = tid >> 1;
    int pa = rows[arow];
    const __half* a_row = L2TAG ? (g_hf + (size_t)pa * KDIM)
                                : (g_xf + (size_t)(pa >> 1) * KDIM);
    const char* a_src = (const char*)(a_row + kbase) + (tid & 1) * 32;
    uint32_t a_dst = sb + SOFF_STAGE + (uint32_t)arow * 80 + (tid & 1) * 32;

    // ---- W: LDG float4 mapping (4 per thread) ----
    const float* wp[4];
    uint32_t woff[4];
#pragma unroll
    for (int j = 0; j < 4; j++) {
        int s = tid + j * 256;
        int r = s >> 3;
        int k4 = (s & 7) << 2;
        wp[j] = W + ((size_t)(n0 + r) * NEXP + e) * KDIM + kbase + k4;
        woff[j] = (uint32_t)r * 80 + (uint32_t)k4 * 2;
    }

    constexpr int NCH = KLOC / BK;

    // ---- fragment addressing (validated R2/R5/R6) ----
    int wm = wid & 1, wn = wid >> 1;
    int li = lane >> 3, lr = lane & 7;
    uint32_t aoff = (uint32_t)((wm * 64 + lr + (li & 1) * 8) * 80 + (li >> 1) * 16);
    uint32_t boff = (uint32_t)((wn * 32 + (li >> 1) * 8 + lr) * 80 + (li & 1) * 16);

    float acc[4][4][4];
#pragma unroll
    for (int im = 0; im < 4; im++)
#pragma unroll
        for (int in = 0; in < 4; in++)
#pragma unroll
            for (int q = 0; q < 4; q++) acc[im][in][q] = 0.0f;

    // ---- prologue ----
    cp16(a_dst, a_src);
    cp16(a_dst + 16, a_src + 16);
    cp_commit();
    float4 wreg[4];
#pragma unroll
    for (int j = 0; j < 4; j++) wreg[j] = *(const float4*)(wp[j]);

    for (int i = 0; i < NCH; i++) {
        uint32_t st = sb + SOFF_STAGE + (uint32_t)(i & 1) * STAGE_BYTES;
        char* stc = smem + SOFF_STAGE + (size_t)(i & 1) * STAGE_BYTES;

        // stage W chunk i (fp32 -> fp16)
#pragma unroll
        for (int j = 0; j < 4; j++)
            conv_sts(stc, A_BYTES + woff[j], wreg[j]);

        cp_wait<0>();
        __syncthreads();

        // issue A chunk i+1 into the other buffer
        if (i + 1 < NCH) {
            uint32_t nst = sb + SOFF_STAGE + (uint32_t)((i + 1) & 1) * STAGE_BYTES
                         + (a_dst - (sb + SOFF_STAGE));
            int kb = (i + 1) * BK * 2;
            cp16(nst, a_src + kb);
            cp16(nst + 16, a_src + kb + 16);
        }
        cp_commit();

        // prefetch W chunk i+1
        if (i + 1 < NCH) {
            int k0 = (i + 1) * BK;
#pragma unroll
            for (int j = 0; j < 4; j++) wreg[j] = *(const float4*)(wp[j] + k0);
        }

        // compute chunk i — B frags double-buffered across the two k16 groups
        uint32_t As = st, Bs = st + A_BYTES;
        uint32_t bf[2][4][2];
        {
            uint32_t t4[4];
            ldm4(t4, Bs + boff);
            bf[0][0][0] = t4[0]; bf[0][0][1] = t4[1];
            bf[0][1][0] = t4[2]; bf[0][1][1] = t4[3];
            ldm4(t4, Bs + boff + 1280);
            bf[0][2][0] = t4[0]; bf[0][2][1] = t4[1];
            bf[0][3][0] = t4[2]; bf[0][3][1] = t4[3];
        }
#pragma unroll
        for (int kk = 0; kk < BK; kk += 16) {
            int cur = (kk >> 4) & 1;
            if (kk + 16 < BK) {
                uint32_t t4[4];
                ldm4(t4, Bs + boff + (kk + 16) * 2);
                bf[cur ^ 1][0][0] = t4[0]; bf[cur ^ 1][0][1] = t4[1];
                bf[cur ^ 1][1][0] = t4[2]; bf[cur ^ 1][1][1] = t4[3];
                ldm4(t4, Bs + boff + 1280 + (kk + 16) * 2);
                bf[cur ^ 1][2][0] = t4[0]; bf[cur ^ 1][2][1] = t4[1];
                bf[cur ^ 1][3][0] = t4[2]; bf[cur ^ 1][3][1] = t4[3];
            }
#pragma unroll
            for (int im = 0; im < 4; im++) {
                uint32_t af[4];
                ldm4(af, As + aoff + im * 1280 + kk * 2);
#pragma unroll
                for (int in = 0; in < 4; in++)
                    mma_f16(acc[im][in], af, bf[cur][in]);
            }
        }
    }

    // ---- epilogue ----
    int qr = lane >> 2, qc = (lane & 3) * 2;
#pragma unroll
    for (int im = 0; im < 4; im++) {
#pragma unroll
        for (int half = 0; half < 2; half++) {
            int m_loc = wm * 64 + im * 16 + qr + half * 8;
            if (m0 + m_loc >= cnt) continue;
            int p = rows[m_loc];
            if (!L2TAG) {
                __half* hp = g_hf + (size_t)p * FDIM;
                const float* bb = bias + (size_t)e * FDIM;
#pragma unroll
                for (int in = 0; in < 4; in++) {
                    int col = n0 + wn * 32 + in * 8 + qc;
                    float v0 = acc[im][in][half * 2 + 0] + bb[col];
                    float v1 = acc[im][in][half * 2 + 1] + bb[col + 1];
                    __half2 hv = __halves2half2(__float2half_rn(gelu_tanh(v0)),
                                                __float2half_rn(gelu_tanh(v1)));
                    *reinterpret_cast<uint32_t*>(hp + col) = *(uint32_t*)&hv;
                }
            } else {
                float pr = g_prob[p];
                float* op = dout + (size_t)(p >> 1) * DDIM;
                const float* bb = bias + (size_t)e * DDIM;
#pragma unroll
                for (int in = 0; in < 4; in++) {
                    int col = n0 + wn * 32 + in * 8 + qc;
                    float b0 = (ks == 0) ? bb[col] : 0.0f;
                    float b1 = (ks == 0) ? bb[col + 1] : 0.0f;
                    atomicAdd(&op[col],
                              pr * (acc[im][in][half * 2 + 0] + b0));
                    atomicAdd(&op[col + 1],
                              pr * (acc[im][in][half * 2 + 1] + b1));
                }
            }
        }
    }
}

// ---------------- launch --------------------------------------------------------------
extern "C" void kernel_launch(void* const* d_in, const int* in_sizes, int n_in,
                              void* d_out, int out_size)
{
    (void)in_sizes; (void)n_in; (void)out_size;
    const float* x  = (const float*)d_in[0];
    const float* gw = (const float*)d_in[1];
    const float* w1 = (const float*)d_in[2];
    const float* b1 = (const float*)d_in[3];
    const float* w2 = (const float*)d_in[4];
    const float* b2 = (const float*)d_in[5];
    float* out = (float*)d_out;

    cudaFuncSetAttribute(moe_fp16<DDIM, false>,
                         cudaFuncAttributeMaxDynamicSharedMemorySize, SMEM_BYTES);
    cudaFuncSetAttribute(moe_fp16<FDIM, true>,
                         cudaFuncAttributeMaxDynamicSharedMemorySize, SMEM_BYTES);

    zero_kernel<<<(TOKENS * DDIM + 255) / 256, 256>>>(out, TOKENS * DDIM);
    gate_kernel<<<TOKENS, 256>>>(x, gw);

    dim3 g1(FDIM / BN, TOKENS / BM, NEXP);        // 32 x 32 x 8
    moe_fp16<DDIM, false><<<g1, NTH, SMEM_BYTES>>>(w1, b1, nullptr);

    dim3 g2((DDIM / BN) * 2, TOKENS / BM, NEXP);  // (8*2) x 32 x 8, k-split
    moe_fp16<FDIM, true><<<g2, NTH, SMEM_BYTES>>>(w2, b2, out);
}